// round 7
// baseline (speedup 1.0000x reference)
#include <cuda_runtime.h>
#include <cuda_bf16.h>
#include <cstdint>

#define B_   8
#define NF_  2048
#define NK_  4096
#define T_   6144
#define CIN_ 256
#define CKQ_ 64
#define COUT_ 256

typedef __nv_bfloat16 bf16;

// bf16 scratch (static device arrays: allocation-free per harness rules)
__device__ __align__(256) bf16 g_Q[(size_t)B_ * NF_ * CKQ_];    // 2 MB (prescaled 1/8)
__device__ __align__(256) bf16 g_K[(size_t)B_ * NK_ * CKQ_];    // 4 MB
__device__ __align__(256) bf16 g_V[(size_t)B_ * NK_ * COUT_];   // 16 MB
__device__ __align__(256) bf16 g_Fb[(size_t)B_ * T_ * CIN_];    // 25 MB features bf16
__device__ __align__(256) bf16 g_Wq[CKQ_ * CIN_];
__device__ __align__(256) bf16 g_Wk[CKQ_ * CIN_];
__device__ __align__(256) bf16 g_Wv[COUT_ * CIN_];

// ---------------------------------------------------------------------------
// PTX helpers
// ---------------------------------------------------------------------------
__device__ __forceinline__ uint32_t smem_u32(const void* p) {
    return (uint32_t)__cvta_generic_to_shared(p);
}
__device__ __forceinline__ void cp16(bf16* dst, const bf16* src) {
    asm volatile("cp.async.cg.shared.global [%0], [%1], 16;\n"
                 :: "r"(smem_u32(dst)), "l"(src));
}
__device__ __forceinline__ void ldsm4(uint32_t& a0, uint32_t& a1, uint32_t& a2,
                                      uint32_t& a3, uint32_t addr) {
    asm volatile("ldmatrix.sync.aligned.m8n8.x4.shared.b16 {%0,%1,%2,%3}, [%4];\n"
                 : "=r"(a0), "=r"(a1), "=r"(a2), "=r"(a3) : "r"(addr));
}
__device__ __forceinline__ void ldsm4t(uint32_t& a0, uint32_t& a1, uint32_t& a2,
                                       uint32_t& a3, uint32_t addr) {
    asm volatile("ldmatrix.sync.aligned.m8n8.x4.trans.shared.b16 {%0,%1,%2,%3}, [%4];\n"
                 : "=r"(a0), "=r"(a1), "=r"(a2), "=r"(a3) : "r"(addr));
}
__device__ __forceinline__ void mma16816(float* c, uint32_t a0, uint32_t a1,
                                         uint32_t a2, uint32_t a3,
                                         uint32_t b0, uint32_t b1) {
    asm volatile("mma.sync.aligned.m16n8k16.row.col.f32.bf16.bf16.f32 "
                 "{%0,%1,%2,%3}, {%4,%5,%6,%7}, {%8,%9}, {%0,%1,%2,%3};\n"
                 : "+f"(c[0]), "+f"(c[1]), "+f"(c[2]), "+f"(c[3])
                 : "r"(a0), "r"(a1), "r"(a2), "r"(a3), "r"(b0), "r"(b1));
}
__device__ __forceinline__ uint32_t bf2u(float a, float b) {
    __nv_bfloat162 h = __floats2bfloat162_rn(a, b);
    return *reinterpret_cast<uint32_t*>(&h);
}

// ---------------------------------------------------------------------------
// fp32 -> bf16 conversions
// ---------------------------------------------------------------------------
__global__ void f2bf(const float4* __restrict__ in, uint2* __restrict__ out, long n4)
{
    for (long i = blockIdx.x * (long)blockDim.x + threadIdx.x; i < n4;
         i += (long)gridDim.x * blockDim.x) {
        float4 v = in[i];
        out[i] = make_uint2(bf2u(v.x, v.y), bf2u(v.z, v.w));
    }
}

// all three weight matrices in one launch
__global__ void f2bf_w(const float4* __restrict__ wq, const float4* __restrict__ wk,
                       const float4* __restrict__ wv,
                       uint2* __restrict__ oq, uint2* __restrict__ ok2,
                       uint2* __restrict__ ov)
{
    int i = blockIdx.x * blockDim.x + threadIdx.x;
    if (i < CKQ_ * CIN_ / 4) {
        float4 a = wq[i];
        oq[i] = make_uint2(bf2u(a.x, a.y), bf2u(a.z, a.w));
        float4 b = wk[i];
        ok2[i] = make_uint2(bf2u(b.x, b.y), bf2u(b.z, b.w));
    }
    if (i < COUT_ * CIN_ / 4) {
        float4 c = wv[i];
        ov[i] = make_uint2(bf2u(c.x, c.y), bf2u(c.z, c.w));
    }
}

// ---------------------------------------------------------------------------
// Projection GEMM on tensor cores (bf16 in, fp32 accum, bf16 out)
// CTA tile 128 x NT, 8 warps, K chunks of 64, cp.async double-buffered.
// ---------------------------------------------------------------------------
template <int NT>
__global__ __launch_bounds__(256) void proj_mma(
    const bf16* __restrict__ Fb, const bf16* __restrict__ W,
    const float* __restrict__ bias, bf16* __restrict__ Y,
    int Mper, int base, int Ntot, float scale)
{
    extern __shared__ bf16 smx[];
    const int BUF = 128 * 72 + NT * 72;     // elems per buffer
    bf16* As = smx;
    bf16* Bs = smx + 128 * 72;

    const int t = threadIdx.x;
    const int w = t >> 5, lane = t & 31;
    const int m0 = blockIdx.x * 128;
    const int n0 = blockIdx.y * NT;
    const int b  = m0 / Mper;
    const int r0 = m0 - b * Mper;
    const bf16* Ag = Fb + ((size_t)b * T_ + base + r0) * CIN_;
    const bf16* Wg = W + (size_t)n0 * CIN_;

    {
        #pragma unroll
        for (int i = 0; i < 4; i++) {
            int c = t + i * 256; int row = c >> 3, ch = c & 7;
            cp16(As + row * 72 + ch * 8, Ag + (size_t)row * CIN_ + ch * 8);
        }
        #pragma unroll
        for (int i = 0; i < NT / 32; i++) {
            int c = t + i * 256; int row = c >> 3, ch = c & 7;
            cp16(Bs + row * 72 + ch * 8, Wg + (size_t)row * CIN_ + ch * 8);
        }
        asm volatile("cp.async.commit_group;\n");
    }

    float acc[2 * (NT / 16)][4];
    #pragma unroll
    for (int j = 0; j < 2 * (NT / 16); j++) {
        acc[j][0] = 0.f; acc[j][1] = 0.f; acc[j][2] = 0.f; acc[j][3] = 0.f;
    }

    const uint32_t a_off = (uint32_t)(((w * 16 + (lane & 15)) * 72 + ((lane >> 4) << 3)) * 2);
    const int b_row16 = ((lane >> 4) << 3) + (lane & 7);
    const int b_col8  = ((lane >> 3) & 1) << 3;

    for (int kc = 0; kc < 4; kc++) {
        __syncthreads();
        if (kc + 1 < 4) {
            int buf = (kc + 1) & 1;
            int k0 = (kc + 1) * 64;
            bf16* Ad = smx + buf * BUF;
            bf16* Bd = Ad + 128 * 72;
            #pragma unroll
            for (int i = 0; i < 4; i++) {
                int c = t + i * 256; int row = c >> 3, ch = c & 7;
                cp16(Ad + row * 72 + ch * 8, Ag + (size_t)row * CIN_ + k0 + ch * 8);
            }
            #pragma unroll
            for (int i = 0; i < NT / 32; i++) {
                int c = t + i * 256; int row = c >> 3, ch = c & 7;
                cp16(Bd + row * 72 + ch * 8, Wg + (size_t)row * CIN_ + k0 + ch * 8);
            }
        }
        asm volatile("cp.async.commit_group;\n");
        asm volatile("cp.async.wait_group 1;\n");
        __syncthreads();

        const uint32_t abase = smem_u32(smx + (kc & 1) * BUF);
        const uint32_t bbase = abase + 128 * 72 * 2;

        #pragma unroll
        for (int ks = 0; ks < 4; ks++) {
            uint32_t a0, a1, a2, a3;
            ldsm4(a0, a1, a2, a3, abase + a_off + ks * 32);
            #pragma unroll
            for (int jp = 0; jp < NT / 16; jp++) {
                uint32_t b0, b1, b2, b3;
                ldsm4(b0, b1, b2, b3,
                      bbase + (uint32_t)(((jp * 16 + b_row16) * 72 + ks * 16 + b_col8) * 2));
                mma16816(acc[2 * jp],     a0, a1, a2, a3, b0, b1);
                mma16816(acc[2 * jp + 1], a0, a1, a2, a3, b2, b3);
            }
        }
    }

    const int r = lane >> 2, qr = lane & 3;
    const size_t grow = (size_t)b * Mper + r0 + w * 16 + r;
    #pragma unroll
    for (int jp = 0; jp < NT / 16; jp++) {
        #pragma unroll
        for (int h = 0; h < 2; h++) {
            int col = n0 + jp * 16 + h * 8 + qr * 2;
            float b0f = __ldg(bias + col), b1f = __ldg(bias + col + 1);
            float* c = acc[2 * jp + h];
            uint32_t lo = bf2u((c[0] + b0f) * scale, (c[1] + b1f) * scale);
            uint32_t hi = bf2u((c[2] + b0f) * scale, (c[3] + b1f) * scale);
            *(uint32_t*)(Y + grow * Ntot + col)       = lo;
            *(uint32_t*)(Y + (grow + 8) * Ntot + col) = hi;
        }
    }
}

// ---------------------------------------------------------------------------
// Keep-row passthrough (fp32, exact)
// ---------------------------------------------------------------------------
__global__ void copy_keep(const float4* __restrict__ f, float4* __restrict__ o)
{
    const int per = NK_ * (COUT_ / 4);
    const size_t total = (size_t)B_ * per;
    for (size_t i = blockIdx.x * (size_t)blockDim.x + threadIdx.x; i < total;
         i += (size_t)gridDim.x * blockDim.x) {
        size_t b = i / per;
        size_t r = i - b * per;
        size_t idx = ((size_t)b * T_ + NF_) * (COUT_ / 4) + r;
        o[idx] = f[idx];
    }
}

// ---------------------------------------------------------------------------
// Flash attention (bf16 mma.sync): CTA = 128 fill rows, Bc = 64 keys/tile.
// S-phase: warp w -> rows 16w..16w+15 x all 64 keys (softmax fully in-warp).
// PV-phase: warp pair (w>>1) -> rows 32*(w>>1)..+31; warp handles 128 V cols
//           selected by (w&1). P staged via smem (stride 72, conflict-free).
// smem (bf16 elems): Qs 9216 | Ks 2*4608 | Vs 2*16896 | Ps 9216 | stats 512B
// ---------------------------------------------------------------------------
#define QS_OFF   0
#define KS_OFF   9216
#define VS_OFF   18432
#define PS_OFF   52224
#define ST_OFF   61440           // elem offset of float stats
#define ATTN_SMEM_BYTES (61440 * 2 + 256 * 4)   // 123904

__global__ __launch_bounds__(256) void attn_kernel(
    const bf16* __restrict__ Q, const bf16* __restrict__ K,
    const bf16* __restrict__ V, float* __restrict__ out)
{
    extern __shared__ bf16 smx[];
    bf16* Qs  = smx + QS_OFF;
    bf16* Ksb = smx + KS_OFF;
    bf16* Vsb = smx + VS_OFF;
    bf16* Ps  = smx + PS_OFF;
    float* sm_c = (float*)(smx + ST_OFF);       // [128]
    float* sm_l = sm_c + 128;                   // [128]

    const int t = threadIdx.x;
    const int w = t >> 5, lane = t & 31;
    const int b = blockIdx.y, mt = blockIdx.x;

    const bf16* Qg = Q + ((size_t)b * NF_ + mt * 128) * 64;
    const bf16* Kg = K + (size_t)b * NK_ * 64;
    const bf16* Vg = V + (size_t)b * NK_ * 256;

    #pragma unroll
    for (int i = 0; i < 4; i++) {
        int c = t + i * 256;
        int row = c >> 3, ch = c & 7;
        cp16(Qs + row * 72 + ch * 8, Qg + row * 64 + ch * 8);
    }
    asm volatile("cp.async.commit_group;\n");

    #pragma unroll
    for (int i = 0; i < 2; i++) {
        int c = t + i * 256; int row = c >> 3, ch = c & 7;
        cp16(Ksb + row * 72 + ch * 8, Kg + row * 64 + ch * 8);
    }
    #pragma unroll
    for (int i = 0; i < 8; i++) {
        int c = t + i * 256; int row = c >> 5, ch = c & 31;
        cp16(Vsb + row * 264 + ch * 8, Vg + row * 256 + ch * 8);
    }
    asm volatile("cp.async.commit_group;\n");

    // O accumulators: rows 32*(w>>1)..+31 (2 m16 tiles) x 128 cols (16 n8)
    float o[2][16][4];
    #pragma unroll
    for (int mi = 0; mi < 2; mi++)
        #pragma unroll
        for (int n = 0; n < 16; n++) {
            o[mi][n][0] = 0.f; o[mi][n][1] = 0.f; o[mi][n][2] = 0.f; o[mi][n][3] = 0.f;
        }
    float m0 = -1e30f, m1 = -1e30f, l0 = 0.f, l1 = 0.f;

    const uint32_t qaddr = smem_u32(Qs + (w * 16 + (lane & 15)) * 72 + ((lane >> 4) << 3));
    const uint32_t pbase = smem_u32(Ps);
    const int k_row16 = ((lane >> 4) << 3) + (lane & 7);
    const int k_col8  = ((lane >> 3) & 1) << 3;
    const int v_row   = lane & 15;
    const int v_col8  = (lane >> 4) << 3;
    const int q4 = lane >> 2, qc = lane & 3;
    const int pairbase = (w >> 1) << 5;       // PV row base
    const int halfoff  = (w & 1) << 7;        // PV col base (0 or 128)

    for (int kt = 0; kt < 64; kt++) {
        __syncthreads();   // all warps done with PV(kt-1) and P reads
        if (kt + 1 < 64) {
            int buf = (kt + 1) & 1;
            const bf16* Kt = Kg + (size_t)(kt + 1) * 64 * 64;
            const bf16* Vt = Vg + (size_t)(kt + 1) * 64 * 256;
            bf16* Kd = Ksb + buf * 4608;
            bf16* Vd = Vsb + buf * 16896;
            #pragma unroll
            for (int i = 0; i < 2; i++) {
                int c = t + i * 256; int row = c >> 3, ch = c & 7;
                cp16(Kd + row * 72 + ch * 8, Kt + row * 64 + ch * 8);
            }
            #pragma unroll
            for (int i = 0; i < 8; i++) {
                int c = t + i * 256; int row = c >> 5, ch = c & 31;
                cp16(Vd + row * 264 + ch * 8, Vt + row * 256 + ch * 8);
            }
        }
        asm volatile("cp.async.commit_group;\n");
        asm volatile("cp.async.wait_group 1;\n");
        __syncthreads();

        const int cur = kt & 1;
        const uint32_t kbase = smem_u32(Ksb + cur * 4608);
        const uint32_t vbase = smem_u32(Vsb + cur * 16896);

        // ---- S = Q K^T : warp w, rows 16w..+15 x 64 keys ----
        float s[8][4];
        #pragma unroll
        for (int j = 0; j < 8; j++) { s[j][0]=0.f; s[j][1]=0.f; s[j][2]=0.f; s[j][3]=0.f; }
        #pragma unroll
        for (int ks = 0; ks < 4; ks++) {
            uint32_t a0, a1, a2, a3;
            ldsm4(a0, a1, a2, a3, qaddr + ks * 32);
            #pragma unroll
            for (int jp = 0; jp < 4; jp++) {
                uint32_t b0, b1, b2, b3;
                ldsm4(b0, b1, b2, b3,
                      kbase + (uint32_t)(((16 * jp + k_row16) * 72 + ks * 16 + k_col8) * 2));
                mma16816(s[2 * jp],     a0, a1, a2, a3, b0, b1);
                mma16816(s[2 * jp + 1], a0, a1, a2, a3, b2, b3);
            }
        }

        // ---- online softmax (rows fully in-warp) ----
        float mx0 = -1e30f, mx1 = -1e30f;
        #pragma unroll
        for (int j = 0; j < 8; j++) {
            mx0 = fmaxf(mx0, fmaxf(s[j][0], s[j][1]));
            mx1 = fmaxf(mx1, fmaxf(s[j][2], s[j][3]));
        }
        mx0 = fmaxf(mx0, __shfl_xor_sync(0xffffffffu, mx0, 1));
        mx0 = fmaxf(mx0, __shfl_xor_sync(0xffffffffu, mx0, 2));
        mx1 = fmaxf(mx1, __shfl_xor_sync(0xffffffffu, mx1, 1));
        mx1 = fmaxf(mx1, __shfl_xor_sync(0xffffffffu, mx1, 2));
        float mn0 = fmaxf(m0, mx0), mn1 = fmaxf(m1, mx1);
        float c0 = __expf(m0 - mn0), c1 = __expf(m1 - mn1);
        m0 = mn0; m1 = mn1;

        float rs0 = 0.f, rs1 = 0.f;
        {
            bf16* Pr0 = Ps + (w * 16 + q4) * 72 + qc * 2;
            bf16* Pr1 = Ps + (w * 16 + 8 + q4) * 72 + qc * 2;
            #pragma unroll
            for (int j = 0; j < 8; j++) {
                float p0 = __expf(s[j][0] - mn0), p1 = __expf(s[j][1] - mn0);
                float p2 = __expf(s[j][2] - mn1), p3 = __expf(s[j][3] - mn1);
                rs0 += p0 + p1; rs1 += p2 + p3;
                *(uint32_t*)(Pr0 + j * 8) = bf2u(p0, p1);
                *(uint32_t*)(Pr1 + j * 8) = bf2u(p2, p3);
            }
        }
        rs0 += __shfl_xor_sync(0xffffffffu, rs0, 1);
        rs0 += __shfl_xor_sync(0xffffffffu, rs0, 2);
        rs1 += __shfl_xor_sync(0xffffffffu, rs1, 1);
        rs1 += __shfl_xor_sync(0xffffffffu, rs1, 2);
        l0 = l0 * c0 + rs0;
        l1 = l1 * c1 + rs1;
        if (qc == 0) {
            sm_c[w * 16 + q4]     = c0;
            sm_c[w * 16 + 8 + q4] = c1;
        }
        __syncthreads();   // P + rescale factors visible to all warps

        // ---- conditional O rescale (rare after early tiles) ----
        float cA0 = sm_c[pairbase + q4];
        float cB0 = sm_c[pairbase + 8 + q4];
        float cA1 = sm_c[pairbase + 16 + q4];
        float cB1 = sm_c[pairbase + 24 + q4];
        bool need = !(cA0 == 1.f && cB0 == 1.f && cA1 == 1.f && cB1 == 1.f);
        if (__any_sync(0xffffffffu, need)) {
            #pragma unroll
            for (int n = 0; n < 16; n++) {
                o[0][n][0] *= cA0; o[0][n][1] *= cA0;
                o[0][n][2] *= cB0; o[0][n][3] *= cB0;
                o[1][n][0] *= cA1; o[1][n][1] *= cA1;
                o[1][n][2] *= cB1; o[1][n][3] *= cB1;
            }
        }

        // ---- O += P V : rows pairbase..+31, cols halfoff..+127 ----
        #pragma unroll
        for (int kf = 0; kf < 4; kf++) {
            uint32_t pa[2][4];
            #pragma unroll
            for (int mi = 0; mi < 2; mi++)
                ldsm4(pa[mi][0], pa[mi][1], pa[mi][2], pa[mi][3],
                      pbase + (uint32_t)(((pairbase + mi * 16 + (lane & 15)) * 72 +
                                          kf * 16 + ((lane >> 4) << 3)) * 2));
            #pragma unroll
            for (int np = 0; np < 8; np++) {
                uint32_t b0, b1, b2, b3;
                ldsm4t(b0, b1, b2, b3,
                       vbase + (uint32_t)(((kf * 16 + v_row) * 264 + halfoff +
                                           np * 16 + v_col8) * 2));
                mma16816(o[0][2 * np],     pa[0][0], pa[0][1], pa[0][2], pa[0][3], b0, b1);
                mma16816(o[0][2 * np + 1], pa[0][0], pa[0][1], pa[0][2], pa[0][3], b2, b3);
                mma16816(o[1][2 * np],     pa[1][0], pa[1][1], pa[1][2], pa[1][3], b0, b1);
                mma16816(o[1][2 * np + 1], pa[1][0], pa[1][1], pa[1][2], pa[1][3], b2, b3);
            }
        }
    }

    // ---- epilogue ----
    if (qc == 0) {
        sm_l[w * 16 + q4]     = l0;
        sm_l[w * 16 + 8 + q4] = l1;
    }
    __syncthreads();
    float invA0 = 1.f / sm_l[pairbase + q4];
    float invB0 = 1.f / sm_l[pairbase + 8 + q4];
    float invA1 = 1.f / sm_l[pairbase + 16 + q4];
    float invB1 = 1.f / sm_l[pairbase + 24 + q4];

    const size_t row0 = (size_t)b * T_ + mt * 128 + pairbase + q4;
    #pragma unroll
    for (int mi = 0; mi < 2; mi++) {
        float ia = mi ? invA1 : invA0;
        float ib = mi ? invB1 : invB0;
        float* oa = out + (row0 + mi * 16) * 256 + halfoff + qc * 2;
        float* ob = out + (row0 + mi * 16 + 8) * 256 + halfoff + qc * 2;
        #pragma unroll
        for (int n = 0; n < 16; n++) {
            *(float2*)(oa + n * 8) = make_float2(o[mi][n][0] * ia, o[mi][n][1] * ia);
            *(float2*)(ob + n * 8) = make_float2(o[mi][n][2] * ib, o[mi][n][3] * ib);
        }
    }
}

// ---------------------------------------------------------------------------
extern "C" void kernel_launch(void* const* d_in, const int* in_sizes, int n_in,
                              void* d_out, int out_size)
{
    (void)in_sizes; (void)n_in; (void)out_size;
    const float* features = (const float*)d_in[0];
    const float* Wq = (const float*)d_in[2];
    const float* bq = (const float*)d_in[3];
    const float* Wk = (const float*)d_in[4];
    const float* bk = (const float*)d_in[5];
    const float* Wv = (const float*)d_in[6];
    const float* bv = (const float*)d_in[7];
    float* out = (float*)d_out;

    bf16 *qp, *kp, *vp, *fb, *wq, *wk, *wv;
    cudaGetSymbolAddress((void**)&qp, g_Q);
    cudaGetSymbolAddress((void**)&kp, g_K);
    cudaGetSymbolAddress((void**)&vp, g_V);
    cudaGetSymbolAddress((void**)&fb, g_Fb);
    cudaGetSymbolAddress((void**)&wq, g_Wq);
    cudaGetSymbolAddress((void**)&wk, g_Wk);
    cudaGetSymbolAddress((void**)&wv, g_Wv);

    // bf16 conversions (launch 1, 2)
    f2bf<<<1024, 256>>>((const float4*)features, (uint2*)fb, (long)B_ * T_ * CIN_ / 4);
    f2bf_w<<<64, 256>>>((const float4*)Wq, (const float4*)Wk, (const float4*)Wv,
                        (uint2*)wq, (uint2*)wk, (uint2*)wv);

    // Tensor-core projections (launches 3-5; Q prescaled by 0.125)
    const int smem64  = 2 * (128 * 72 + 64 * 72) * 2;
    const int smem256 = 2 * (128 * 72 + 256 * 72) * 2;
    cudaFuncSetAttribute(proj_mma<64>, cudaFuncAttributeMaxDynamicSharedMemorySize, smem64);
    cudaFuncSetAttribute(proj_mma<256>, cudaFuncAttributeMaxDynamicSharedMemorySize, smem256);
    proj_mma<64><<<dim3((B_ * NF_) / 128, 1), 256, smem64>>>(fb, wq, bq, qp, NF_, 0, CKQ_, 0.125f);
    proj_mma<64><<<dim3((B_ * NK_) / 128, 1), 256, smem64>>>(fb, wk, bk, kp, NK_, NF_, CKQ_, 1.f);
    proj_mma<256><<<dim3((B_ * NK_) / 128, 1), 256, smem256>>>(fb, wv, bv, vp, NK_, NF_, COUT_, 1.f);

    // Flash attention over fill rows (launch 6 -> ncu -s 5 -c 1 captures this)
    cudaFuncSetAttribute(attn_kernel, cudaFuncAttributeMaxDynamicSharedMemorySize,
                         ATTN_SMEM_BYTES);
    attn_kernel<<<dim3(NF_ / 128, B_), 256, ATTN_SMEM_BYTES>>>(qp, kp, vp, out);

    // Passthrough of keep rows (launch 7, independent)
    copy_keep<<<2048, 256>>>((const float4*)features, (float4*)out);
}